// round 10
// baseline (speedup 1.0000x reference)
#include <cuda_runtime.h>

#define GN     128
#define GMASK  127
#define NCELLS (GN * GN * GN)

// grid scratch: [cell][2 float4] = 64 MB, plain z-major
__device__ float4 g_grid[NCELLS * 2];

// ---------------- P2G: 16 lanes/point, 2 points/warp (at REDG lane-op floor ~63us) --------
__global__ __launch_bounds__(256)
void p2g_coop(const float* __restrict__ pos,
              const float4* __restrict__ feat4, int n) {
    int lane = threadIdx.x & 31;
    int warp = (blockIdx.x * blockDim.x + threadIdx.x) >> 5;
    int i = warp * 2 + (lane >> 4);
    if (i >= n) return;

    int k = lane & 15;
    int node = k >> 1;
    int half = k & 1;
    int ox = node >> 2, oy = (node >> 1) & 1, oz = node & 1;

    float rx = __ldg(&pos[3 * i + 0]) * (float)GN;
    float ry = __ldg(&pos[3 * i + 1]) * (float)GN;
    float rz = __ldg(&pos[3 * i + 2]) * (float)GN;
    int bx = (int)rx, by = (int)ry, bz = (int)rz;
    float fx = rx - (float)bx, fy = ry - (float)by, fz = rz - (float)bz;

    float w = (ox ? fx : 1.0f - fx) * (oy ? fy : 1.0f - fy) * (oz ? fz : 1.0f - fz);

    float4 f = __ldg(&feat4[2 * i + half]);

    int nx = (bx + ox) & GMASK;
    int ny = (by + oy) & GMASK;
    int nz = (bz + oz) & GMASK;
    int nid = ((nx << 7 | ny) << 7) | nz;

    float4 c = make_float4(w * f.x, w * f.y, w * f.z, w * f.w);
    atomicAdd(&g_grid[2 * nid + half], c);
}

// ---------------- G2P: 8 lanes/point, 4 points/THREAD, real MLP=8 this time ----------------
// lane = p*8 + s;  s: oy=bit2, oz=bit1, half=bit0.  Thread handles points
// i_m = warp*16 + p + 4*m.  __launch_bounds__(256,3) gives ptxas an ~85-reg budget
// so all 8 grid LDG.128 stay in flight (r9 was clamped to 32 regs -> serialized).
struct PtCtx { float wA, wB; int nidA, nidB; };

__device__ __forceinline__ PtCtx g2p_setup(const float* __restrict__ pos, int i,
                                           int oy, int oz) {
    float rx = __ldg(&pos[3 * i + 0]) * (float)GN;
    float ry = __ldg(&pos[3 * i + 1]) * (float)GN;
    float rz = __ldg(&pos[3 * i + 2]) * (float)GN;
    int bx = (int)rx, by = (int)ry, bz = (int)rz;
    float fx = rx - (float)bx, fy = ry - (float)by, fz = rz - (float)bz;

    float wyz = (oy ? fy : 1.0f - fy) * (oz ? fz : 1.0f - fz);
    PtCtx c;
    c.wA = (1.0f - fx) * wyz;
    c.wB = fx * wyz;
    int ny = (by + oy) & GMASK;
    int nz = (bz + oz) & GMASK;
    c.nidA = ((bx << 7 | ny) << 7) | nz;                  // bx in [0,127]: no mask
    c.nidB = ((((bx + 1) & GMASK) << 7 | ny) << 7) | nz;
    return c;
}

__device__ __forceinline__ float g2p_reduce(float v0, float v1, float v2, float v3,
                                            bool soz, bool soy) {
    float t, r, a0, a1;
    t = soz ? v0 : v2;  r = __shfl_xor_sync(0xffffffffu, t, 2);
    a0 = (soz ? v2 : v0) + r;
    t = soz ? v1 : v3;  r = __shfl_xor_sync(0xffffffffu, t, 2);
    a1 = (soz ? v3 : v1) + r;
    t = soy ? a0 : a1;  r = __shfl_xor_sync(0xffffffffu, t, 4);
    return (soy ? a1 : a0) + r;
}

__global__ __launch_bounds__(256, 3)
void g2p_split4(const float* __restrict__ pos,
                float* __restrict__ out, int n) {
    int lane = threadIdx.x & 31;
    int warp = (blockIdx.x * blockDim.x + threadIdx.x) >> 5;
    int p = lane >> 3;
    int s = lane & 7;

    int oy = (s >> 2) & 1;
    int oz = (s >> 1) & 1;
    int half = s & 1;
    bool soz = oz != 0, soy = oy != 0;

    int base = warp * 16 + p;
    int i0 = base, i1 = base + 4, i2 = base + 8, i3 = base + 12;
    bool a0 = i0 < n, a1 = i1 < n, a2 = i2 < n, a3 = i3 < n;
    int ic0 = a0 ? i0 : (n - 1), ic1 = a1 ? i1 : (n - 1);
    int ic2 = a2 ? i2 : (n - 1), ic3 = a3 ? i3 : (n - 1);

    PtCtx c0 = g2p_setup(pos, ic0, oy, oz);
    PtCtx c1 = g2p_setup(pos, ic1, oy, oz);
    PtCtx c2 = g2p_setup(pos, ic2, oy, oz);
    PtCtx c3 = g2p_setup(pos, ic3, oy, oz);

    // 8 independent LDG.128 — with the raised reg budget these all batch
    float4 gA0 = __ldg(&g_grid[2 * c0.nidA + half]);
    float4 gB0 = __ldg(&g_grid[2 * c0.nidB + half]);
    float4 gA1 = __ldg(&g_grid[2 * c1.nidA + half]);
    float4 gB1 = __ldg(&g_grid[2 * c1.nidB + half]);
    float4 gA2 = __ldg(&g_grid[2 * c2.nidA + half]);
    float4 gB2 = __ldg(&g_grid[2 * c2.nidB + half]);
    float4 gA3 = __ldg(&g_grid[2 * c3.nidA + half]);
    float4 gB3 = __ldg(&g_grid[2 * c3.nidB + half]);

    float r0 = g2p_reduce(c0.wA * gA0.x + c0.wB * gB0.x,
                          c0.wA * gA0.y + c0.wB * gB0.y,
                          c0.wA * gA0.z + c0.wB * gB0.z,
                          c0.wA * gA0.w + c0.wB * gB0.w, soz, soy);
    float r1 = g2p_reduce(c1.wA * gA1.x + c1.wB * gB1.x,
                          c1.wA * gA1.y + c1.wB * gB1.y,
                          c1.wA * gA1.z + c1.wB * gB1.z,
                          c1.wA * gA1.w + c1.wB * gB1.w, soz, soy);
    float r2 = g2p_reduce(c2.wA * gA2.x + c2.wB * gB2.x,
                          c2.wA * gA2.y + c2.wB * gB2.y,
                          c2.wA * gA2.z + c2.wB * gB2.z,
                          c2.wA * gA2.w + c2.wB * gB2.w, soz, soy);
    float r3 = g2p_reduce(c3.wA * gA3.x + c3.wB * gB3.x,
                          c3.wA * gA3.y + c3.wB * gB3.y,
                          c3.wA * gA3.z + c3.wB * gB3.z,
                          c3.wA * gA3.w + c3.wB * gB3.w, soz, soy);

    int comp = half * 4 + oz * 2 + oy;
    if (a0) out[8 * (size_t)i0 + comp] = r0;
    if (a1) out[8 * (size_t)i1 + comp] = r1;
    if (a2) out[8 * (size_t)i2 + comp] = r2;
    if (a3) out[8 * (size_t)i3 + comp] = r3;
}

extern "C" void kernel_launch(void* const* d_in, const int* in_sizes, int n_in,
                              void* d_out, int out_size) {
    const float* pos  = (const float*)d_in[0];   // [N,3] f32
    const float* feat = (const float*)d_in[1];   // [N,8] f32
    float* out        = (float*)d_out;           // [N,8] f32
    int n = in_sizes[0] / 3;

    void* gptr = nullptr;
    cudaGetSymbolAddress(&gptr, g_grid);
    cudaMemsetAsync(gptr, 0, (size_t)NCELLS * 2 * sizeof(float4), 0);

    // p2g: 16 lanes/point -> 16 points per 256-thread block
    int pb = (n + 15) / 16;
    p2g_coop<<<pb, 256>>>(pos, (const float4*)feat, n);

    // g2p: 8 lanes/point, 4 pts/thread -> 128 points per 256-thread block
    int gb = (n + 127) / 128;
    g2p_split4<<<gb, 256>>>(pos, (float*)out, n);
}

// round 11
// speedup vs baseline: 1.6692x; 1.6692x over previous
#include <cuda_runtime.h>
#include <cuda_fp16.h>

#define GN     128
#define GMASK  127
#define NCELLS (GN * GN * GN)

// grid scratch: one 16B record per cell = 8 fp16 features. 32 MB.
__device__ uint4 g_gridh[NCELLS];

// ---------------- P2G: 8 lanes/point, 4 points/warp, one 16B fp16 red per node ------------
// lane = p*8 + s;  s = node id: ox=bit2, oy=bit1, oz=bit0.
__global__ __launch_bounds__(256)
void p2g_h(const float* __restrict__ pos,
           const float4* __restrict__ feat4, int n) {
    int lane = threadIdx.x & 31;
    int warp = (blockIdx.x * blockDim.x + threadIdx.x) >> 5;
    int i = warp * 4 + (lane >> 3);
    if (i >= n) return;

    int s = lane & 7;
    int ox = (s >> 2) & 1, oy = (s >> 1) & 1, oz = s & 1;

    float rx = __ldg(&pos[3 * i + 0]) * (float)GN;
    float ry = __ldg(&pos[3 * i + 1]) * (float)GN;
    float rz = __ldg(&pos[3 * i + 2]) * (float)GN;
    int bx = (int)rx, by = (int)ry, bz = (int)rz;
    float fx = rx - (float)bx, fy = ry - (float)by, fz = rz - (float)bz;

    float w = (ox ? fx : 1.0f - fx) * (oy ? fy : 1.0f - fy) * (oz ? fz : 1.0f - fz);

    float4 f0 = __ldg(&feat4[2 * i + 0]);   // broadcast across the point's 8 lanes
    float4 f1 = __ldg(&feat4[2 * i + 1]);

    int nx = (bx + ox) & GMASK;
    int ny = (by + oy) & GMASK;
    int nz = (bz + oz) & GMASK;
    int nid = ((nx << 7 | ny) << 7) | nz;

    __half2 h01 = __floats2half2_rn(w * f0.x, w * f0.y);
    __half2 h23 = __floats2half2_rn(w * f0.z, w * f0.w);
    __half2 h45 = __floats2half2_rn(w * f1.x, w * f1.y);
    __half2 h67 = __floats2half2_rn(w * f1.z, w * f1.w);

    asm volatile(
        "red.global.add.noftz.v4.f16x2 [%0], {%1, %2, %3, %4};"
        :: "l"(&g_gridh[nid]),
           "r"(*reinterpret_cast<const unsigned*>(&h01)),
           "r"(*reinterpret_cast<const unsigned*>(&h23)),
           "r"(*reinterpret_cast<const unsigned*>(&h45)),
           "r"(*reinterpret_cast<const unsigned*>(&h67))
        : "memory");
}

// ---------------- G2P: 4 lanes/point, 2 points/thread (16 pts/warp), fp16 grid ------------
// lane = pp*4 + s;  s: oy=bit1, oz=bit0.  Lane loads BOTH ox records of node (oy,oz);
// ox summed in registers. Butterfly: oz (xor1) halves 8->4 comps, oy (xor2) 4->2.
// Final lane holds comps {oz*4+oy*2, +1} -> one coalesced STG.64 per point.
struct PtCtxH { float wA, wB; int nidA, nidB; };

__device__ __forceinline__ PtCtxH g2p_setup_h(const float* __restrict__ pos, int i,
                                              int oy, int oz) {
    float rx = __ldg(&pos[3 * i + 0]) * (float)GN;
    float ry = __ldg(&pos[3 * i + 1]) * (float)GN;
    float rz = __ldg(&pos[3 * i + 2]) * (float)GN;
    int bx = (int)rx, by = (int)ry, bz = (int)rz;
    float fx = rx - (float)bx, fy = ry - (float)by, fz = rz - (float)bz;

    float wyz = (oy ? fy : 1.0f - fy) * (oz ? fz : 1.0f - fz);
    PtCtxH c;
    c.wA = (1.0f - fx) * wyz;
    c.wB = fx * wyz;
    int ny = (by + oy) & GMASK;
    int nz = (bz + oz) & GMASK;
    c.nidA = ((bx << 7 | ny) << 7) | nz;
    c.nidB = ((((bx + 1) & GMASK) << 7 | ny) << 7) | nz;
    return c;
}

// v[8] = wA*recA + wB*recB, fp16 records converted to f32
__device__ __forceinline__ void cvt_fma8(const uint4& ra, const uint4& rb,
                                         float wA, float wB, float* v) {
    const __half2* ha = reinterpret_cast<const __half2*>(&ra);
    const __half2* hb = reinterpret_cast<const __half2*>(&rb);
    #pragma unroll
    for (int k = 0; k < 4; k++) {
        float2 fa = __half22float2(ha[k]);
        float2 fb = __half22float2(hb[k]);
        v[2 * k + 0] = wA * fa.x + wB * fb.x;
        v[2 * k + 1] = wA * fa.y + wB * fb.y;
    }
}

// butterfly for one point: oz level (xor1, halve 8->4), oy level (xor2, 4->2)
__device__ __forceinline__ float2 g2p_reduce_h(float* v, bool soz, bool soy) {
    float t, r, a0, a1, a2, a3;
    // oz: keep comps 0..3 (oz=0) or 4..7 (oz=1); exchange the other block
    t = soz ? v[0] : v[4];  r = __shfl_xor_sync(0xffffffffu, t, 1);
    a0 = (soz ? v[4] : v[0]) + r;
    t = soz ? v[1] : v[5];  r = __shfl_xor_sync(0xffffffffu, t, 1);
    a1 = (soz ? v[5] : v[1]) + r;
    t = soz ? v[2] : v[6];  r = __shfl_xor_sync(0xffffffffu, t, 1);
    a2 = (soz ? v[6] : v[2]) + r;
    t = soz ? v[3] : v[7];  r = __shfl_xor_sync(0xffffffffu, t, 1);
    a3 = (soz ? v[7] : v[3]) + r;
    // oy: keep pair {0,1} (oy=0) or {2,3} (oy=1)
    float b0, b1;
    t = soy ? a0 : a2;  r = __shfl_xor_sync(0xffffffffu, t, 2);
    b0 = (soy ? a2 : a0) + r;
    t = soy ? a1 : a3;  r = __shfl_xor_sync(0xffffffffu, t, 2);
    b1 = (soy ? a3 : a1) + r;
    return make_float2(b0, b1);   // comps {oz*4+oy*2, +1}
}

__global__ __launch_bounds__(256, 5)
void g2p_h(const float* __restrict__ pos,
           float2* __restrict__ out2, int n) {
    int lane = threadIdx.x & 31;
    int warp = (blockIdx.x * blockDim.x + threadIdx.x) >> 5;
    int pp = lane >> 2;
    int s = lane & 3;
    int oy = (s >> 1) & 1;
    int oz = s & 1;
    bool soz = oz != 0, soy = oy != 0;

    int i0 = warp * 16 + pp;
    int i1 = i0 + 8;
    bool a0 = i0 < n, a1 = i1 < n;
    int ic0 = a0 ? i0 : (n - 1);
    int ic1 = a1 ? i1 : (n - 1);

    PtCtxH c0 = g2p_setup_h(pos, ic0, oy, oz);
    PtCtxH c1 = g2p_setup_h(pos, ic1, oy, oz);

    // 4 independent 16B loads
    uint4 rA0 = __ldg(&g_gridh[c0.nidA]);
    uint4 rB0 = __ldg(&g_gridh[c0.nidB]);
    uint4 rA1 = __ldg(&g_gridh[c1.nidA]);
    uint4 rB1 = __ldg(&g_gridh[c1.nidB]);

    float v0[8], v1[8];
    cvt_fma8(rA0, rB0, c0.wA, c0.wB, v0);
    cvt_fma8(rA1, rB1, c1.wA, c1.wB, v1);

    float2 r0 = g2p_reduce_h(v0, soz, soy);
    float2 r1 = g2p_reduce_h(v1, soz, soy);

    int cpair = oz * 2 + oy;          // float2 index within the point's 4 pairs
    if (a0) out2[4 * (size_t)i0 + cpair] = r0;
    if (a1) out2[4 * (size_t)i1 + cpair] = r1;
}

extern "C" void kernel_launch(void* const* d_in, const int* in_sizes, int n_in,
                              void* d_out, int out_size) {
    const float* pos  = (const float*)d_in[0];   // [N,3] f32
    const float* feat = (const float*)d_in[1];   // [N,8] f32
    float* out        = (float*)d_out;           // [N,8] f32
    int n = in_sizes[0] / 3;

    void* gptr = nullptr;
    cudaGetSymbolAddress(&gptr, g_gridh);
    cudaMemsetAsync(gptr, 0, (size_t)NCELLS * sizeof(uint4), 0);

    // p2g: 8 lanes/point -> 32 points per 256-thread block
    int pb = (n + 31) / 32;
    p2g_h<<<pb, 256>>>(pos, (const float4*)feat, n);

    // g2p: 4 lanes/point, 2 pts/thread -> 128 points per 256-thread block
    int gb = (n + 127) / 128;
    g2p_h<<<gb, 256>>>(pos, (float2*)out, n);
}

// round 13
// speedup vs baseline: 1.6831x; 1.0083x over previous
#include <cuda_runtime.h>
#include <cuda_fp16.h>

#define GN     128
#define GMASK  127
#define NCELLS (GN * GN * GN)

// grid scratch: one 16B record per cell = 8 fp16 features. 32 MB.
__device__ uint4 g_gridh[NCELLS];

__device__ __forceinline__ unsigned h2_to_u(__half2 h) {
    return *reinterpret_cast<unsigned*>(&h);
}
__device__ __forceinline__ __half2 u_to_h2(unsigned u) {
    return *reinterpret_cast<__half2*>(&u);
}

// ---------------- P2G: 8 lanes/point, 4 points/warp, one 16B fp16 red per node ------------
// lane = p*8 + s;  s = node id: ox=bit2, oy=bit1, oz=bit0.  (at REDG lane-op floor)
__global__ __launch_bounds__(256)
void p2g_h(const float* __restrict__ pos,
           const float4* __restrict__ feat4, int n) {
    int lane = threadIdx.x & 31;
    int warp = (blockIdx.x * blockDim.x + threadIdx.x) >> 5;
    int i = warp * 4 + (lane >> 3);
    if (i >= n) return;

    int s = lane & 7;
    int ox = (s >> 2) & 1, oy = (s >> 1) & 1, oz = s & 1;

    float rx = __ldg(&pos[3 * i + 0]) * (float)GN;
    float ry = __ldg(&pos[3 * i + 1]) * (float)GN;
    float rz = __ldg(&pos[3 * i + 2]) * (float)GN;
    int bx = (int)rx, by = (int)ry, bz = (int)rz;
    float fx = rx - (float)bx, fy = ry - (float)by, fz = rz - (float)bz;

    float w = (ox ? fx : 1.0f - fx) * (oy ? fy : 1.0f - fy) * (oz ? fz : 1.0f - fz);

    float4 f0 = __ldg(&feat4[2 * i + 0]);
    float4 f1 = __ldg(&feat4[2 * i + 1]);

    int nx = (bx + ox) & GMASK;
    int ny = (by + oy) & GMASK;
    int nz = (bz + oz) & GMASK;
    int nid = ((nx << 7 | ny) << 7) | nz;

    __half2 h01 = __floats2half2_rn(w * f0.x, w * f0.y);
    __half2 h23 = __floats2half2_rn(w * f0.z, w * f0.w);
    __half2 h45 = __floats2half2_rn(w * f1.x, w * f1.y);
    __half2 h67 = __floats2half2_rn(w * f1.z, w * f1.w);

    asm volatile(
        "red.global.add.noftz.v4.f16x2 [%0], {%1, %2, %3, %4};"
        :: "l"(&g_gridh[nid]),
           "r"(h2_to_u(h01)), "r"(h2_to_u(h23)),
           "r"(h2_to_u(h45)), "r"(h2_to_u(h67))
        : "memory");
}

// ---------------- G2P: 4 lanes/point, 2 points/thread, half2 math end-to-end --------------
// lane = pp*4 + s;  s: oy=bit1, oz=bit0.  Lane loads both ox-records of node (oy,oz),
// combines with 4 HMUL2 + 4 HFMA2, then a packed-half2 butterfly:
//   oz (xor1): exchange 2 regs, 2 HADD2  -> comps oz*4 + {0..3}
//   oy (xor2): exchange 1 reg,  1 HADD2  -> comps oz*4 + oy*2 + {0,1}
// Convert final half2 -> float2, one coalesced 8B store per point per lane group.
struct PtCtxH { __half2 wA2, wB2; int nidA, nidB; };

__device__ __forceinline__ PtCtxH g2p_setup_h(const float* __restrict__ pos, int i,
                                              int oy, int oz) {
    float rx = __ldg(&pos[3 * i + 0]) * (float)GN;
    float ry = __ldg(&pos[3 * i + 1]) * (float)GN;
    float rz = __ldg(&pos[3 * i + 2]) * (float)GN;
    int bx = (int)rx, by = (int)ry, bz = (int)rz;
    float fx = rx - (float)bx, fy = ry - (float)by, fz = rz - (float)bz;

    float wyz = (oy ? fy : 1.0f - fy) * (oz ? fz : 1.0f - fz);
    PtCtxH c;
    c.wA2 = __half2half2(__float2half_rn((1.0f - fx) * wyz));
    c.wB2 = __half2half2(__float2half_rn(fx * wyz));
    int ny = (by + oy) & GMASK;
    int nz = (bz + oz) & GMASK;
    c.nidA = ((bx << 7 | ny) << 7) | nz;
    c.nidB = ((((bx + 1) & GMASK) << 7 | ny) << 7) | nz;
    return c;
}

__device__ __forceinline__ float2 g2p_combine_h(const uint4& ra, const uint4& rb,
                                                const PtCtxH& c, bool soz, bool soy) {
    const __half2* ha = reinterpret_cast<const __half2*>(&ra);
    const __half2* hb = reinterpret_cast<const __half2*>(&rb);
    __half2 v0 = __hfma2(hb[0], c.wB2, __hmul2(ha[0], c.wA2));
    __half2 v1 = __hfma2(hb[1], c.wB2, __hmul2(ha[1], c.wA2));
    __half2 v2 = __hfma2(hb[2], c.wB2, __hmul2(ha[2], c.wA2));
    __half2 v3 = __hfma2(hb[3], c.wB2, __hmul2(ha[3], c.wA2));

    // oz exchange (xor 1): keep regs {v2,v3} if oz else {v0,v1}; send the other pair
    unsigned t, r;
    __half2 a0, a1;
    t = h2_to_u(soz ? v0 : v2);
    r = __shfl_xor_sync(0xffffffffu, t, 1);
    a0 = __hadd2(soz ? v2 : v0, u_to_h2(r));
    t = h2_to_u(soz ? v1 : v3);
    r = __shfl_xor_sync(0xffffffffu, t, 1);
    a1 = __hadd2(soz ? v3 : v1, u_to_h2(r));

    // oy exchange (xor 2): keep a1 if oy else a0
    t = h2_to_u(soy ? a0 : a1);
    r = __shfl_xor_sync(0xffffffffu, t, 2);
    __half2 b = __hadd2(soy ? a1 : a0, u_to_h2(r));

    return __half22float2(b);
}

__global__ __launch_bounds__(256, 6)
void g2p_h2(const float* __restrict__ pos,
            float2* __restrict__ out2, int n) {
    int lane = threadIdx.x & 31;
    int warp = (blockIdx.x * blockDim.x + threadIdx.x) >> 5;
    int pp = lane >> 2;
    int s = lane & 3;
    int oy = (s >> 1) & 1;
    int oz = s & 1;
    bool soz = oz != 0, soy = oy != 0;

    int i0 = warp * 16 + pp;
    int i1 = i0 + 8;
    bool a0 = i0 < n, a1 = i1 < n;
    int ic0 = a0 ? i0 : (n - 1);
    int ic1 = a1 ? i1 : (n - 1);

    PtCtxH c0 = g2p_setup_h(pos, ic0, oy, oz);
    PtCtxH c1 = g2p_setup_h(pos, ic1, oy, oz);

    // 4 independent 16B loads
    uint4 rA0 = __ldg(&g_gridh[c0.nidA]);
    uint4 rB0 = __ldg(&g_gridh[c0.nidB]);
    uint4 rA1 = __ldg(&g_gridh[c1.nidA]);
    uint4 rB1 = __ldg(&g_gridh[c1.nidB]);

    float2 r0 = g2p_combine_h(rA0, rB0, c0, soz, soy);
    float2 r1 = g2p_combine_h(rA1, rB1, c1, soz, soy);

    int cpair = oz * 2 + oy;
    if (a0) out2[4 * (size_t)i0 + cpair] = r0;
    if (a1) out2[4 * (size_t)i1 + cpair] = r1;
}

extern "C" void kernel_launch(void* const* d_in, const int* in_sizes, int n_in,
                              void* d_out, int out_size) {
    const float* pos  = (const float*)d_in[0];   // [N,3] f32
    const float* feat = (const float*)d_in[1];   // [N,8] f32
    float* out        = (float*)d_out;           // [N,8] f32
    int n = in_sizes[0] / 3;

    void* gptr = nullptr;
    cudaGetSymbolAddress(&gptr, g_gridh);
    cudaMemsetAsync(gptr, 0, (size_t)NCELLS * sizeof(uint4), 0);

    // p2g: 8 lanes/point -> 32 points per 256-thread block
    int pb = (n + 31) / 32;
    p2g_h<<<pb, 256>>>(pos, (const float4*)feat, n);

    // g2p: 4 lanes/point, 2 pts/thread -> 128 points per 256-thread block
    int gb = (n + 127) / 128;
    g2p_h2<<<gb, 256>>>(pos, (float2*)out, n);
}